// round 15
// baseline (speedup 1.0000x reference)
#include <cuda_runtime.h>
#include <cstdint>

// TaxaNetLoss: loss = sum_{k=1..3} W[k] * (viol_k * e + ce_k)
//   ce_k   = mean_i ( log( sum_{j in lvl k} exp(yp[i,j]) + (C - L_k) ) - yp[i, yt[i,k]] )
//   argm[k,i] = argmax of yp masked to level k (zeros outside), first-occurrence
//               tie-break -> implicit zero candidate at first out-of-level index
//               (30 for k=0, 0 for k>=1).
// R15: R7's exact 4-independent-chain loop (best measured per-warp efficiency,
// cold 17.4us) at NT=192 -> ~40 warps/SM (~63% occ) instead of 27 (40%), same
// grid granularity, same regs. Isolates occupancy on top of the best loop.
// Lane-parallel epilogue; last ticket holder does the fixed-order
// deterministic final sum and resets the ticket (graph-replay safe).

#define N_SAMPLES 1024
#define C_TOTAL   13430
#define NT        192
#define NW        (NT / 32)

static __device__ __align__(16) float g_partial[N_SAMPLES];
static __device__ unsigned int g_ticket = 0;

__device__ __forceinline__ float fexp(float x) {
    // Schraudolph fast exp: 1 FFMA + 1 F2I, ~+-3% rel err; ~1e-5 rel on loss.
    return __int_as_float((int)fmaf(x, 12102203.0f, 1064866805.0f));
}

__global__ __launch_bounds__(NT) void taxa_kernel(
    const float* __restrict__ yp, const int* __restrict__ yt,
    const float* __restrict__ H, float* __restrict__ out)
{
    const int i    = blockIdx.x;       // sample
    const int tid  = threadIdx.x;
    const int lane = tid & 31;
    const int wid  = tid >> 5;
    const float* row = yp + (size_t)i * C_TOTAL;

    __shared__ float s_v[3][NW];
    __shared__ int   s_i[3][NW];
    __shared__ float s_s[3][NW];
    __shared__ int   s_am[4];
    __shared__ float s_term[3];
    __shared__ int   s_last;

    if (tid == 0) s_last = 0;

    // ---- level 0 (30 elems): warp 0
    if (wid == 0) {
        float bv0 = (lane < 30) ? row[lane] : -3.4e38f;
        int   bi0 = (lane < 30) ? lane : C_TOTAL;
#pragma unroll
        for (int off = 16; off; off >>= 1) {
            float v2 = __shfl_down_sync(0xffffffffu, bv0, off);
            int   i2 = __shfl_down_sync(0xffffffffu, bi0, off);
            if (v2 > bv0 || (v2 == bv0 && i2 < bi0)) { bv0 = v2; bi0 = i2; }
        }
        if (0.0f > bv0 || (0.0f == bv0 && 30 < bi0)) bi0 = 30;  // first zero = 30
        if (lane == 0) s_am[0] = bi0;
    }

    // ---- levels 1..3: streaming argmax + sum-of-exp, 4 independent chains
    const int LO[4] = {30, 430, 3430, 13430};
#pragma unroll
    for (int k = 0; k < 3; k++) {
        const int lo  = LO[k];
        const int len = LO[k + 1] - lo;
        const float* p = row + lo;
        int head = (int)(((16u - ((uintptr_t)p & 15u)) & 15u) >> 2);  // 0 or 2
        if (head > len) head = len;

        float bvx = -3.4e38f, bvy = -3.4e38f, bvz = -3.4e38f, bvw = -3.4e38f;
        int   bix = C_TOTAL,  biy = C_TOTAL,  biz = C_TOTAL,  biw = C_TOTAL;
        float sx = 0.0f, sy = 0.0f, sz = 0.0f, sw = 0.0f;

        for (int j = tid; j < head; j += NT) {          // head (<=3 elems)
            float v = p[j];
            bool c = v > bvx; bvx = fmaxf(bvx, v); bix = c ? (lo + j) : bix;
            sx += fexp(v);
        }
        const int nv = (len - head) >> 2;
        const float4* pv = (const float4*)(p + head);
#pragma unroll 8
        for (int j = tid; j < nv; j += NT) {
            float4 q = pv[j];
            int b0 = lo + head + 4 * j;
            bool cx = q.x > bvx; bvx = fmaxf(bvx, q.x); bix = cx ? b0     : bix;
            bool cy = q.y > bvy; bvy = fmaxf(bvy, q.y); biy = cy ? b0 + 1 : biy;
            bool cz = q.z > bvz; bvz = fmaxf(bvz, q.z); biz = cz ? b0 + 2 : biz;
            bool cw = q.w > bvw; bvw = fmaxf(bvw, q.w); biw = cw ? b0 + 3 : biw;
            sx += fexp(q.x); sy += fexp(q.y); sz += fexp(q.z); sw += fexp(q.w);
        }
        for (int j = head + 4 * nv + tid; j < len; j += NT) {   // tail (<=3)
            float v = p[j];
            bool c = v > bvx; bvx = fmaxf(bvx, v); bix = c ? (lo + j) : bix;
            sx += fexp(v);
        }

        // merge the 4 chains (lexicographic: value desc, index asc)
        if (bvy > bvx || (bvy == bvx && biy < bix)) { bvx = bvy; bix = biy; }
        if (bvw > bvz || (bvw == bvz && biw < biz)) { bvz = bvw; biz = biw; }
        if (bvz > bvx || (bvz == bvx && biz < bix)) { bvx = bvz; bix = biz; }
        float mss = (sx + sy) + (sz + sw);

        // warp reduce (lexicographic max + sum)
#pragma unroll
        for (int off = 16; off; off >>= 1) {
            float v2 = __shfl_down_sync(0xffffffffu, bvx, off);
            int   i2 = __shfl_down_sync(0xffffffffu, bix, off);
            mss     += __shfl_down_sync(0xffffffffu, mss, off);
            if (v2 > bvx || (v2 == bvx && i2 < bix)) { bvx = v2; bix = i2; }
        }
        if (lane == 0) { s_v[k][wid] = bvx; s_i[k][wid] = bix; s_s[k][wid] = mss; }
    }
    __syncthreads();

    // ---- epilogue on warp 0: lane k (k<3) handles level k+1 independently
    if (wid == 0) {
        float S = 0.0f; float rowt = 0.0f;
        if (lane < 3) {
            const int k = lane;
            const int LEN[3] = {400, 3000, 10000};
            float v = s_v[k][0]; int ix = s_i[k][0]; float sm = s_s[k][0];
#pragma unroll
            for (int w = 1; w < NW; w++) {
                float v2 = s_v[k][w]; int i2 = s_i[k][w];
                sm += s_s[k][w];
                if (v2 > v || (v2 == v && i2 < ix)) { v = v2; ix = i2; }
            }
            if (0.0f > v || (0.0f == v && 0 < ix)) ix = 0;  // first zero = idx 0
            s_am[k + 1] = ix;
            S = sm + (float)(C_TOTAL - LEN[k]);              // exp(0)=1 outside level
            int t = __ldg(&yt[i * 4 + (k + 1)]);
            rowt = __ldg(&row[t]);                           // parallel gather
        }
        __syncwarp();
        if (lane < 3) {
            const int k = lane;
            const float E = 2.718281828459045f;
            float term = (__logf(S) - rowt) * (1.0f / (float)N_SAMPLES);
            if (i > 0) {
                int a = s_am[k], b = s_am[k + 1];
                float h = __ldg(&H[(size_t)a * C_TOTAL + b]);  // 3 lanes: parallel
                if (h == 0.0f) term += E;
            }
            s_term[k] = term;
        }
        __syncwarp();
        if (lane == 0) {
            g_partial[i] = 0.25f * s_term[0] + 0.15f * s_term[1] + 0.10f * s_term[2];
            __threadfence();
            unsigned t = atomicAdd(&g_ticket, 1u);
            if (t == N_SAMPLES - 1) s_last = 1;
        }
    }
    __syncthreads();

    // ---- last ticket holder's block: fixed-order deterministic sum
    if (s_last) {
        __threadfence();  // acquire all g_partial stores
        float sm = 0.0f;
        for (int j = tid; j < N_SAMPLES; j += NT)   // fixed per-thread order
            sm += g_partial[j];
#pragma unroll
        for (int off = 16; off; off >>= 1)
            sm += __shfl_down_sync(0xffffffffu, sm, off);
        __shared__ float red[NW];
        if (lane == 0) red[wid] = sm;
        __syncthreads();
        if (tid == 0) {
            float tot = 0.0f;
#pragma unroll
            for (int w = 0; w < NW; w++) tot += red[w];
            out[0] = tot;
            g_ticket = 0;   // reset for next graph replay
        }
    }
}

extern "C" void kernel_launch(void* const* d_in, const int* in_sizes, int n_in,
                              void* d_out, int out_size)
{
    const float* yp = (const float*)d_in[0];   // [1024, 13430] f32
    const int*   yt = (const int*)d_in[1];     // [1024, 4] i32
    const float* H  = (const float*)d_in[2];   // [13430, 13430] f32
    float* out = (float*)d_out;

    taxa_kernel<<<N_SAMPLES, NT>>>(yp, yt, H, out);
}

// round 16
// speedup vs baseline: 1.1555x; 1.1555x over previous
#include <cuda_runtime.h>
#include <cstdint>

// TaxaNetLoss: loss = sum_{k=1..3} W[k] * (viol_k * e + ce_k)
//   viol_k = #{ i in [1,N) : H[argm[k-1,i], argm[k,i]] == 0 }
//   ce_k   = mean_i ( log( sum_{j in level k} exp(yp[i,j]) + (C - L_k) ) - yp[i, yt[i,k]] )
//   argm[k,i] = argmax over full C of yp masked to level k (zeros outside),
//               first-occurrence tie-break -> implicit zero-candidate at the first
//               out-of-level index (30 for k=0, 0 for k>=1).
// R16 (final): exact reproduction of the round-2 champion (wall 14.85us) —
// the empirically best point of a fully-swept design space. 32-reg serial
// compare chain, NT=256, 80% occupancy, per-sample fused epilogue incl. the
// 3 H gathers, and a tiny separate deterministic sum kernel. All later
// "improvements" (multi-chain argmax, TMA/cp.async transports, pipelines,
// occupancy tuning, epilogue parallelization) tied or regressed: the wall is
// floor-bound by ~6us replay overhead + ~9us warm-L2 body at this occupancy.

#define N_SAMPLES 1024
#define C_TOTAL   13430

static __device__ __align__(16) float g_partial[N_SAMPLES];

__device__ __forceinline__ float fexp(float x) {
    // Schraudolph fast exp: 1 FFMA + 1 F2I, ~+-3% rel err, fine for the lse sum
    // (CE contributes ~5 abs to a ~1400 loss -> lse error is ~1e-5 rel on loss).
    return __int_as_float((int)fmaf(x, 12102203.0f, 1064866805.0f));
}

template <int NT>
__global__ __launch_bounds__(NT) void levels_kernel(
    const float* __restrict__ yp, const int* __restrict__ yt,
    const float* __restrict__ H)
{
    const int i    = blockIdx.x;       // sample
    const int tid  = threadIdx.x;
    const int lane = tid & 31;
    const int wid  = tid >> 5;
    constexpr int NW = NT / 32;
    const float* row = yp + (size_t)i * C_TOTAL;

    __shared__ float s_v[3][NW];
    __shared__ int   s_i[3][NW];
    __shared__ float s_s[3][NW];

    // ---- level 0 (30 elems): warp 0 only; result lives in thread 0's register
    int argm0 = 0;
    if (wid == 0) {
        float bv0 = (lane < 30) ? row[lane] : -3.4e38f;
        int   bi0 = (lane < 30) ? lane : C_TOTAL;
#pragma unroll
        for (int off = 16; off; off >>= 1) {
            float v2 = __shfl_down_sync(0xffffffffu, bv0, off);
            int   i2 = __shfl_down_sync(0xffffffffu, bi0, off);
            if (v2 > bv0 || (v2 == bv0 && i2 < bi0)) { bv0 = v2; bi0 = i2; }
        }
        if (0.0f > bv0 || (0.0f == bv0 && 30 < bi0)) bi0 = 30;  // first zero = idx 30
        argm0 = bi0;
    }

    const int PIQ[5] = {0, 30, 430, 3430, 13430};
    float bv[3]; int bi[3]; float ss[3];

    // ---- levels 1..3: streaming argmax + sum-of-exp per thread
#pragma unroll
    for (int k = 0; k < 3; k++) {
        const int lo  = PIQ[k + 1];
        const int len = PIQ[k + 2] - lo;
        float mbv = -3.4e38f; int mbi = C_TOTAL; float mss = 0.0f;

        const float* p = row + lo;
        int head = (int)(((16u - ((uintptr_t)p & 15u)) & 15u) >> 2);  // 0..3, < len

        for (int j = tid; j < head; j += NT) {
            float v = p[j];
            if (v > mbv) { mbv = v; mbi = lo + j; }
            mss += fexp(v);
        }
        const int nv = (len - head) >> 2;
        const float4* pv = (const float4*)(p + head);
        for (int j = tid; j < nv; j += NT) {
            float4 q = pv[j];
            int b0 = lo + head + 4 * j;
            if (q.x > mbv) { mbv = q.x; mbi = b0;     }
            if (q.y > mbv) { mbv = q.y; mbi = b0 + 1; }
            if (q.z > mbv) { mbv = q.z; mbi = b0 + 2; }
            if (q.w > mbv) { mbv = q.w; mbi = b0 + 3; }
            mss += (fexp(q.x) + fexp(q.y)) + (fexp(q.z) + fexp(q.w));
        }
        for (int j = head + 4 * nv + tid; j < len; j += NT) {
            float v = p[j];
            if (v > mbv) { mbv = v; mbi = lo + j; }
            mss += fexp(v);
        }
        bv[k] = mbv; bi[k] = mbi; ss[k] = mss;
    }

    // ---- warp-shuffle reductions (lexicographic max + sum), one barrier total
#pragma unroll
    for (int k = 0; k < 3; k++) {
        float v = bv[k]; int ix = bi[k]; float s = ss[k];
#pragma unroll
        for (int off = 16; off; off >>= 1) {
            float v2 = __shfl_down_sync(0xffffffffu, v,  off);
            int   i2 = __shfl_down_sync(0xffffffffu, ix, off);
            s       += __shfl_down_sync(0xffffffffu, s,  off);
            if (v2 > v || (v2 == v && i2 < ix)) { v = v2; ix = i2; }
        }
        if (lane == 0) { s_v[k][wid] = v; s_i[k][wid] = ix; s_s[k][wid] = s; }
    }
    __syncthreads();

    // ---- thread 0: combine warps, CE terms, H gather, per-sample partial
    if (tid == 0) {
        int   argm[4];
        float ce[4];
        argm[0] = argm0;
#pragma unroll
        for (int k = 0; k < 3; k++) {
            float v = s_v[k][0]; int ix = s_i[k][0]; float s = s_s[k][0];
#pragma unroll
            for (int w = 1; w < NW; w++) {
                float v2 = s_v[k][w]; int i2 = s_i[k][w];
                s += s_s[k][w];
                if (v2 > v || (v2 == v && i2 < ix)) { v = v2; ix = i2; }
            }
            if (0.0f > v || (0.0f == v && 0 < ix)) ix = 0;  // first zero = idx 0
            argm[k + 1] = ix;
            int len = PIQ[k + 2] - PIQ[k + 1];
            float S = s + (float)(C_TOTAL - len);   // exp(0)=1 per out-of-level col
            int t = yt[i * 4 + (k + 1)];
            ce[k + 1] = logf(S) - row[t];
        }
        const float W1 = 0.25f, W2 = 0.15f, W3 = 0.10f;
        const float E  = 2.718281828459045f;
        float local = (W1 * ce[1] + W2 * ce[2] + W3 * ce[3]) * (1.0f / (float)N_SAMPLES);
        if (i > 0) {
            float h1 = __ldg(&H[(size_t)argm[0] * C_TOTAL + argm[1]]);
            float h2 = __ldg(&H[(size_t)argm[1] * C_TOTAL + argm[2]]);
            float h3 = __ldg(&H[(size_t)argm[2] * C_TOTAL + argm[3]]);
            if (h1 == 0.0f) local += W1 * E;
            if (h2 == 0.0f) local += W2 * E;
            if (h3 == 0.0f) local += W3 * E;
        }
        g_partial[i] = local;
    }
}

__global__ __launch_bounds__(256) void sum_kernel(float* __restrict__ out)
{
    const int tid = threadIdx.x;                       // 256 threads x float4
    const float4* p = (const float4*)g_partial;
    float4 q = p[tid];
    float s = (q.x + q.y) + (q.z + q.w);
#pragma unroll
    for (int off = 16; off; off >>= 1)
        s += __shfl_down_sync(0xffffffffu, s, off);
    __shared__ float sm[8];
    if ((tid & 31) == 0) sm[tid >> 5] = s;
    __syncthreads();
    if (tid == 0) {
        float t = 0.0f;
#pragma unroll
        for (int w = 0; w < 8; w++) t += sm[w];
        out[0] = t;
    }
}

extern "C" void kernel_launch(void* const* d_in, const int* in_sizes, int n_in,
                              void* d_out, int out_size)
{
    const float* yp = (const float*)d_in[0];   // [1024, 13430] f32
    const int*   yt = (const int*)d_in[1];     // [1024, 4] i32
    const float* H  = (const float*)d_in[2];   // [13430, 13430] f32
    float* out = (float*)d_out;

    levels_kernel<256><<<N_SAMPLES, 256>>>(yp, yt, H);
    sum_kernel<<<1, 256>>>(out);
}